// round 11
// baseline (speedup 1.0000x reference)
#include <cuda_runtime.h>
#include <cuda_bf16.h>
#include <cstdint>

#define BB 64
#define SS 8192
#define DDIM 64
#define SPLIT 16
#define ROWS_P1 (SS / SPLIT)   // 512
#define CH 32
#define NCHUNK (ROWS_P1 / CH)  // 16
#define TP 17                  // phase1 tile row stride (words)

__device__ float    g_part[SPLIT * BB * DDIM * DDIM];
__device__ float    g_ksum_part[SPLIT * BB * DDIM];
__device__ uint32_t g_bhi[BB * DDIM * 32];   // kvT bf16-hi packed words [b][e][32]
__device__ uint32_t g_blo[BB * DDIM * 32];
__device__ float    g_ksum[BB * DDIM];

// ---------------- helpers ----------------
__device__ __forceinline__ float fm(float x) { return x > 0.0f ? x + 1.0f : __expf(x); }
__device__ __forceinline__ unsigned su32(const void* p) {
    unsigned r;
    asm("{ .reg .u64 t; cvta.to.shared.u64 t, %1; cvt.u32.u64 %0, t; }" : "=r"(r) : "l"(p));
    return r;
}
__device__ __forceinline__ void cp16(unsigned s, const void* g) {
    asm volatile("cp.async.cg.shared.global [%0], [%1], 16;" :: "r"(s), "l"(g));
}
#define CP_COMMIT() asm volatile("cp.async.commit_group;")
#define CP_WAIT(N)  asm volatile("cp.async.wait_group %0;" :: "n"(N))

__device__ __forceinline__ uint32_t pklh(float lo, float hi) {  // lo -> low 16
    uint32_t r;
    asm("cvt.rn.bf16x2.f32 %0, %1, %2;" : "=r"(r) : "f"(hi), "f"(lo));
    return r;
}
__device__ __forceinline__ uint32_t prmt7632(uint32_t a, uint32_t b) {
    uint32_t r; asm("prmt.b32 %0, %1, %2, 0x7632;" : "=r"(r) : "r"(a), "r"(b)); return r;
}
// truncation split of 2 fp32 -> packed bf16 hi word + bf16 lo word (x0 in low 16)
__device__ __forceinline__ void split2(float x0, float x1, uint32_t& hw, uint32_t& lw) {
    uint32_t u0 = __float_as_uint(x0), u1 = __float_as_uint(x1);
    hw = prmt7632(u0, u1);
    float l0 = x0 - __uint_as_float(u0 & 0xFFFF0000u);
    float l1 = x1 - __uint_as_float(u1 & 0xFFFF0000u);
    lw = pklh(l0, l1);
}
__device__ __forceinline__ void mma_bf16(float* c, const uint32_t* a, uint32_t b0, uint32_t b1) {
    asm volatile("mma.sync.aligned.m16n8k16.row.col.f32.bf16.bf16.f32 "
                 "{%0,%1,%2,%3},{%4,%5,%6,%7},{%8,%9},{%0,%1,%2,%3};"
                 : "+f"(c[0]), "+f"(c[1]), "+f"(c[2]), "+f"(c[3])
                 : "r"(a[0]), "r"(a[1]), "r"(a[2]), "r"(a[3]), "r"(b0), "r"(b1));
}

// ---------------- phase 1: kvT partials via HMMA (proven version) ------------
// D[e][d] = sum_s v[s][e] * kf[s][d];  A = vT (m=e,k=s), B = kfT (k=s,n=d)
#define P1_STG   0        // 2 bufs x (k,v) x 2048 f32 = 32768 B
#define P1_KFH   32768    // [64][TP] words = 4352 B
#define P1_KFL   37120
#define P1_VTH   41472
#define P1_VTL   45824
#define P1_KSUM  50176
#define P1_SMEM  50432

__global__ __launch_bounds__(256) void phase1_kernel(const float* __restrict__ k,
                                                     const float* __restrict__ v) {
    extern __shared__ char smx[];
    uint32_t* kfTh = (uint32_t*)(smx + P1_KFH);
    uint32_t* kfTl = (uint32_t*)(smx + P1_KFL);
    uint32_t* vTh  = (uint32_t*)(smx + P1_VTH);
    uint32_t* vTl  = (uint32_t*)(smx + P1_VTL);
    float* ksum_sm = (float*)(smx + P1_KSUM);

    const int t = threadIdx.x, w = t >> 5, lane = t & 31;
    const int g = lane >> 2, tig = lane & 3;
    const int sx = blockIdx.x, b = blockIdx.y;
    const float* kp = k + ((size_t)b * SS + (size_t)sx * ROWS_P1) * DDIM;
    const float* vp = v + ((size_t)b * SS + (size_t)sx * ROWS_P1) * DDIM;
    const unsigned sstg = su32(smx);

    if (t < 64) ksum_sm[t] = 0.0f;

    // prefetch chunk 0 -> buf0, chunk 1 -> buf1
#pragma unroll
    for (int c = 0; c < 2; c++) {
        const float* kb = kp + (size_t)c * 2048;
        const float* vb = vp + (size_t)c * 2048;
        unsigned d0 = sstg + c * 16384;
        cp16(d0 + t * 16, kb + t * 4);
        cp16(d0 + (t + 256) * 16, kb + (t + 256) * 4);
        cp16(d0 + 8192 + t * 16, vb + t * 4);
        cp16(d0 + 8192 + (t + 256) * 16, vb + (t + 256) * 4);
        CP_COMMIT();
    }

    const int eb = (w & 3) * 16;        // warp m-tile (e rows)
    const int nb = (w >> 2) * 4;        // warp n-tile group (4 tiles of 8 d)
    float acc[4][4];
#pragma unroll
    for (int i = 0; i < 4; i++)
#pragma unroll
        for (int j = 0; j < 4; j++) acc[i][j] = 0.0f;
    float ksl = 0.0f;

    const int td = t & 63, sgb = (t >> 6) * 8;   // transpose-pass mapping

    for (int ch = 0; ch < NCHUNK; ch++) {
        const int buf = ch & 1;
        if (ch < NCHUNK - 1) CP_WAIT(1); else CP_WAIT(0);
        __syncthreads();   // staging ready + previous mma done

        // transpose/convert: k -> fm -> split -> kfT ; v -> split -> vT
        {
            const float* sk = (const float*)(smx + buf * 16384);
            const float* sv = sk + 2048;
            float x[8];
#pragma unroll
            for (int i = 0; i < 8; i++) {
                float y = fm(sk[(sgb + i) * 64 + td]);
                ksl += y; x[i] = y;
            }
#pragma unroll
            for (int j = 0; j < 4; j++) {
                uint32_t hw, lw;
                split2(x[2 * j], x[2 * j + 1], hw, lw);
                kfTh[td * TP + sgb / 2 + j] = hw;
                kfTl[td * TP + sgb / 2 + j] = lw;
            }
#pragma unroll
            for (int i = 0; i < 8; i++) x[i] = sv[(sgb + i) * 64 + td];
#pragma unroll
            for (int j = 0; j < 4; j++) {
                uint32_t hw, lw;
                split2(x[2 * j], x[2 * j + 1], hw, lw);
                vTh[td * TP + sgb / 2 + j] = hw;
                vTl[td * TP + sgb / 2 + j] = lw;
            }
        }
        __syncthreads();   // tiles ready, staging[buf] free

        if (ch + 2 < NCHUNK) {
            const float* kb = kp + (size_t)(ch + 2) * 2048;
            const float* vb = vp + (size_t)(ch + 2) * 2048;
            unsigned d0 = sstg + buf * 16384;
            cp16(d0 + t * 16, kb + t * 4);
            cp16(d0 + (t + 256) * 16, kb + (t + 256) * 4);
            cp16(d0 + 8192 + t * 16, vb + t * 4);
            cp16(d0 + 8192 + (t + 256) * 16, vb + (t + 256) * 4);
            CP_COMMIT();
        }

#pragma unroll
        for (int ks = 0; ks < 2; ks++) {
            const int sp = ks * 8 + tig;
            const int e0 = eb + g;
            uint32_t ah[4], al[4];
            ah[0] = vTh[e0 * TP + sp];       ah[1] = vTh[(e0 + 8) * TP + sp];
            ah[2] = vTh[e0 * TP + sp + 4];   ah[3] = vTh[(e0 + 8) * TP + sp + 4];
            al[0] = vTl[e0 * TP + sp];       al[1] = vTl[(e0 + 8) * TP + sp];
            al[2] = vTl[e0 * TP + sp + 4];   al[3] = vTl[(e0 + 8) * TP + sp + 4];
#pragma unroll
            for (int nt = 0; nt < 4; nt++) {
                const int d0 = (nb + nt) * 8 + g;
                uint32_t bh0 = kfTh[d0 * TP + sp], bh1 = kfTh[d0 * TP + sp + 4];
                uint32_t bl0 = kfTl[d0 * TP + sp], bl1 = kfTl[d0 * TP + sp + 4];
                mma_bf16(acc[nt], ah, bh0, bh1);
                mma_bf16(acc[nt], ah, bl0, bl1);
                mma_bf16(acc[nt], al, bh0, bh1);
            }
        }
    }

    // epilogue: partials [e][d] + ksum
    {
        float* op = g_part + ((size_t)sx * BB + b) * 4096;
#pragma unroll
        for (int nt = 0; nt < 4; nt++) {
            const int e0 = eb + g, d0 = (nb + nt) * 8 + tig * 2;
            *(float2*)(op + (size_t)e0 * 64 + d0)       = make_float2(acc[nt][0], acc[nt][1]);
            *(float2*)(op + (size_t)(e0 + 8) * 64 + d0) = make_float2(acc[nt][2], acc[nt][3]);
        }
    }
    atomicAdd(&ksum_sm[td], ksl);
    __syncthreads();
    if (t < 64) g_ksum_part[((size_t)sx * BB + b) * 64 + t] = ksum_sm[t];
}

// ---------------- combine: sum partials -> bf16 hi/lo word arrays ----------------
__global__ __launch_bounds__(256) void combine_kernel() {
    const int b = blockIdx.x, t = threadIdx.x;
    if (t < 64) {
        float s = 0.0f;
#pragma unroll
        for (int p = 0; p < SPLIT; p++) s += g_ksum_part[((size_t)p * BB + b) * 64 + t];
        g_ksum[(size_t)b * 64 + t] = s;
    }
#pragma unroll
    for (int i = 0; i < 8; i++) {
        const int p = t + i * 256;             // pair index = e*32 + word
        const int e = p >> 5, d0 = (p & 31) * 2;
        float s0 = 0.0f, s1 = 0.0f;
#pragma unroll
        for (int sp = 0; sp < SPLIT; sp++) {
            float2 x = *(const float2*)(g_part + ((size_t)sp * BB + b) * 4096 + (size_t)e * 64 + d0);
            s0 += x.x; s1 += x.y;
        }
        uint32_t hw, lw;
        split2(s0, s1, hw, lw);
        g_bhi[(size_t)b * 2048 + p] = hw;
        g_blo[(size_t)b * 2048 + p] = lw;
    }
}

// ---------------- phase 2: pipelined HMMA, 32-row chunks, 1 wave -------------
// D[s][e] = qf[s][d] * kv[d][e];  A = qf (m=s,k=d), B = kvT words (k=d,n=e)
#define CH2 32             // rows per chunk
#define NC2 32             // chunks per CTA -> 1024 rows
#define QST 68             // q stage row stride (words)
#define AST 36             // tile row stride (words)
#define P2_ST0 0           // 32*QST*4 = 8704 B each
#define P2_ST1 8704
#define P2_AH  17408       // [32][AST] = 4608 B each
#define P2_AL  22016
#define P2_BH  26624       // [64][AST] = 9216 B each
#define P2_BL  35840
#define P2_KS  45056       // 64 f32
#define P2_ID  45312       // 32 f32
#define P2_SMEM 45568

__global__ __launch_bounds__(256, 4) void phase2_kernel(const float* __restrict__ q,
                                                        float* __restrict__ o) {
    extern __shared__ char smx[];
    uint32_t* Ah = (uint32_t*)(smx + P2_AH);
    uint32_t* Al = (uint32_t*)(smx + P2_AL);
    uint32_t* Bh = (uint32_t*)(smx + P2_BH);
    uint32_t* Bl = (uint32_t*)(smx + P2_BL);
    float* ksum_s = (float*)(smx + P2_KS);
    float* iden   = (float*)(smx + P2_ID);
    const unsigned sbase = su32(smx);

    const int t = threadIdx.x, w = t >> 5, lane = t & 31;
    const int g = lane >> 2, tig = lane & 3;
    const int b = blockIdx.y;
    const size_t row0 = (size_t)b * SS + (size_t)blockIdx.x * (NC2 * CH2);
    const float* qp = q + row0 * 64;
    float* op = o + row0 * 64;

    // prologue: B tiles + stage chunk0 (group 1), stage chunk1 (group 2)
    {
        const uint4* gh = (const uint4*)(g_bhi + (size_t)b * 2048);
        const uint4* gl = (const uint4*)(g_blo + (size_t)b * 2048);
#pragma unroll
        for (int i = 0; i < 2; i++) {
            int idx = t + i * 256;
            int e = idx >> 3, w4 = (idx & 7) * 4;
            cp16(sbase + P2_BH + (e * AST + w4) * 4, gh + idx);
            cp16(sbase + P2_BL + (e * AST + w4) * 4, gl + idx);
        }
        // chunk0: 32x64 floats = 512 cp16 -> 2/thread
#pragma unroll
        for (int i = 0; i < 2; i++) {
            int idx = t + i * 256;
            int row = idx >> 4, c4 = (idx & 15) * 4;
            cp16(sbase + P2_ST0 + (row * QST + c4) * 4, qp + (size_t)row * 64 + c4);
        }
        CP_COMMIT();
#pragma unroll
        for (int i = 0; i < 2; i++) {
            int idx = t + i * 256;
            int row = idx >> 4, c4 = (idx & 15) * 4;
            cp16(sbase + P2_ST1 + (row * QST + c4) * 4, qp + (size_t)(CH2 + row) * 64 + c4);
        }
        CP_COMMIT();
    }
    if (t < 64) ksum_s[t] = g_ksum[(size_t)b * 64 + t];

    const int m0 = (w & 1) * 16;       // warp m-tile (rows), 2-way
    const int nbx = (w >> 1) * 16;     // warp n base (cols), 4-way

    for (int c = 0; c < NC2; c++) {
        const int buf = c & 1;
        if (c < NC2 - 1) CP_WAIT(1); else CP_WAIT(0);
        __syncthreads();   // stage[buf] ready + previous MMA done with A

        // convert: fm + denominator + hi/lo split into Ah/Al
        {
            const float* st = (const float*)(smx + (buf ? P2_ST1 : P2_ST0));
            const int row = t >> 3, c8 = (t & 7) * 8;
            const float* sr = st + row * QST + c8;
            float4 x = *(const float4*)(sr);
            float4 y = *(const float4*)(sr + 4);
            x.x = fm(x.x); x.y = fm(x.y); x.z = fm(x.z); x.w = fm(x.w);
            y.x = fm(y.x); y.y = fm(y.y); y.z = fm(y.z); y.w = fm(y.w);
            const float* ks = &ksum_s[c8];
            float pden = x.x * ks[0] + x.y * ks[1] + x.z * ks[2] + x.w * ks[3]
                       + y.x * ks[4] + y.y * ks[5] + y.z * ks[6] + y.w * ks[7];
            uint32_t h0, l0, h1, l1, h2, l2, h3, l3;
            split2(x.x, x.y, h0, l0);
            split2(x.z, x.w, h1, l1);
            split2(y.x, y.y, h2, l2);
            split2(y.z, y.w, h3, l3);
            const int wb = row * AST + (t & 7) * 4;
            *(uint4*)&Ah[wb] = make_uint4(h0, h1, h2, h3);
            *(uint4*)&Al[wb] = make_uint4(l0, l1, l2, l3);
            pden += __shfl_xor_sync(0xffffffffu, pden, 1);
            pden += __shfl_xor_sync(0xffffffffu, pden, 2);
            pden += __shfl_xor_sync(0xffffffffu, pden, 4);
            if (!(t & 7)) iden[row] = 1.0f / fmaxf(pden, 1e-4f);
        }
        __syncthreads();   // A/iden ready, stage[buf] free

        if (c + 2 < NC2) {   // prefetch chunk c+2 (overlaps MMA below)
            const unsigned dst = sbase + (buf ? P2_ST1 : P2_ST0);
            const float* src = qp + (size_t)(c + 2) * CH2 * 64;
#pragma unroll
            for (int i = 0; i < 2; i++) {
                int idx = t + i * 256;
                int row = idx >> 4, c4 = (idx & 15) * 4;
                cp16(dst + (row * QST + c4) * 4, src + (size_t)row * 64 + c4);
            }
            CP_COMMIT();
        }

        float acc[2][4];
#pragma unroll
        for (int i = 0; i < 2; i++)
#pragma unroll
            for (int j = 0; j < 4; j++) acc[i][j] = 0.0f;

#pragma unroll
        for (int ks = 0; ks < 4; ks++) {
            const int cc = ks * 8 + tig;
            const int r = m0 + g;
            uint32_t ah[4], al[4];
            ah[0] = Ah[r * AST + cc];       ah[1] = Ah[(r + 8) * AST + cc];
            ah[2] = Ah[r * AST + cc + 4];   ah[3] = Ah[(r + 8) * AST + cc + 4];
            al[0] = Al[r * AST + cc];       al[1] = Al[(r + 8) * AST + cc];
            al[2] = Al[r * AST + cc + 4];   al[3] = Al[(r + 8) * AST + cc + 4];
#pragma unroll
            for (int nt = 0; nt < 2; nt++) {
                const int e0 = nbx + nt * 8 + g;
                uint32_t bh0 = Bh[e0 * AST + cc], bh1 = Bh[e0 * AST + cc + 4];
                uint32_t bl0 = Bl[e0 * AST + cc], bl1 = Bl[e0 * AST + cc + 4];
                mma_bf16(acc[nt], ah, bh0, bh1);
                mma_bf16(acc[nt], ah, bl0, bl1);
                mma_bf16(acc[nt], al, bh0, bh1);
            }
        }

        // epilogue: scale by 1/deno and store
        {
            float* oc = op + (size_t)(c * CH2) * 64;
            const int r = m0 + g;
            const float i0 = iden[r], i1 = iden[r + 8];
#pragma unroll
            for (int nt = 0; nt < 2; nt++) {
                const int e = nbx + nt * 8 + tig * 2;
                *(float2*)(oc + (size_t)r * 64 + e) =
                    make_float2(acc[nt][0] * i0, acc[nt][1] * i0);
                *(float2*)(oc + (size_t)(r + 8) * 64 + e) =
                    make_float2(acc[nt][2] * i1, acc[nt][3] * i1);
            }
        }
    }
}

// ---------------- launch ----------------
extern "C" void kernel_launch(void* const* d_in, const int* in_sizes, int n_in,
                              void* d_out, int out_size) {
    (void)in_sizes; (void)n_in; (void)out_size;
    const float* q = (const float*)d_in[0];
    const float* k = (const float*)d_in[1];
    const float* v = (const float*)d_in[2];
    float* o = (float*)d_out;

    cudaFuncSetAttribute(phase1_kernel, cudaFuncAttributeMaxDynamicSharedMemorySize, P1_SMEM);
    cudaFuncSetAttribute(phase2_kernel, cudaFuncAttributeMaxDynamicSharedMemorySize, P2_SMEM);

    dim3 g1(SPLIT, BB);
    phase1_kernel<<<g1, 256, P1_SMEM>>>(k, v);

    combine_kernel<<<BB, 256>>>();

    dim3 g2(SS / (NC2 * CH2), BB);
    phase2_kernel<<<g2, 256, P2_SMEM>>>(q, o);
}

// round 12
// speedup vs baseline: 1.1304x; 1.1304x over previous
#include <cuda_runtime.h>
#include <cuda_bf16.h>
#include <cstdint>

#define BB 64
#define SS 8192
#define DDIM 64
#define SPLIT 16
#define ROWS_P1 (SS / SPLIT)   // 512
#define CH 32
#define NCHUNK (ROWS_P1 / CH)  // 16
#define TP 20                  // phase1 tile row stride (words): 4 mod 8 -> conflict-free frag loads

__device__ float    g_part[SPLIT * BB * DDIM * DDIM];
__device__ float    g_ksum_part[SPLIT * BB * DDIM];
__device__ uint32_t g_bhi[BB * DDIM * 32];   // kvT bf16-hi packed words [b][e][32]
__device__ uint32_t g_blo[BB * DDIM * 32];
__device__ float    g_ksum[BB * DDIM];

// ---------------- helpers ----------------
__device__ __forceinline__ float fm(float x) { return x > 0.0f ? x + 1.0f : __expf(x); }
__device__ __forceinline__ unsigned su32(const void* p) {
    unsigned r;
    asm("{ .reg .u64 t; cvta.to.shared.u64 t, %1; cvt.u32.u64 %0, t; }" : "=r"(r) : "l"(p));
    return r;
}
__device__ __forceinline__ void cp16(unsigned s, const void* g) {
    asm volatile("cp.async.cg.shared.global [%0], [%1], 16;" :: "r"(s), "l"(g));
}
#define CP_COMMIT() asm volatile("cp.async.commit_group;")
#define CP_WAIT(N)  asm volatile("cp.async.wait_group %0;" :: "n"(N))

__device__ __forceinline__ uint32_t pklh(float lo, float hi) {  // lo -> low 16
    uint32_t r;
    asm("cvt.rn.bf16x2.f32 %0, %1, %2;" : "=r"(r) : "f"(hi), "f"(lo));
    return r;
}
__device__ __forceinline__ uint32_t prmt7632(uint32_t a, uint32_t b) {
    uint32_t r; asm("prmt.b32 %0, %1, %2, 0x7632;" : "=r"(r) : "r"(a), "r"(b)); return r;
}
// truncation split of 2 fp32 -> packed bf16 hi word + bf16 lo word (x0 in low 16)
__device__ __forceinline__ void split2(float x0, float x1, uint32_t& hw, uint32_t& lw) {
    uint32_t u0 = __float_as_uint(x0), u1 = __float_as_uint(x1);
    hw = prmt7632(u0, u1);
    float l0 = x0 - __uint_as_float(u0 & 0xFFFF0000u);
    float l1 = x1 - __uint_as_float(u1 & 0xFFFF0000u);
    lw = pklh(l0, l1);
}
__device__ __forceinline__ void mma_bf16(float* c, const uint32_t* a, uint32_t b0, uint32_t b1) {
    asm volatile("mma.sync.aligned.m16n8k16.row.col.f32.bf16.bf16.f32 "
                 "{%0,%1,%2,%3},{%4,%5,%6,%7},{%8,%9},{%0,%1,%2,%3};"
                 : "+f"(c[0]), "+f"(c[1]), "+f"(c[2]), "+f"(c[3])
                 : "r"(a[0]), "r"(a[1]), "r"(a[2]), "r"(a[3]), "r"(b0), "r"(b1));
}

// ---------------- phase 1: kvT partials via HMMA ------------------------------
// D[e][d] = sum_s v[s][e] * kf[s][d];  A = vT (m=e,k=s), B = kfT (k=s,n=d)
#define P1_STG   0        // 2 bufs x (k,v) x 2048 f32 = 32768 B
#define P1_KFH   32768    // [64][TP] words = 5120 B each
#define P1_KFL   37888
#define P1_VTH   43008
#define P1_VTL   48128
#define P1_KSUM  53248
#define P1_SMEM  53504

__global__ __launch_bounds__(256) void phase1_kernel(const float* __restrict__ k,
                                                     const float* __restrict__ v) {
    extern __shared__ char smx[];
    uint32_t* kfTh = (uint32_t*)(smx + P1_KFH);
    uint32_t* kfTl = (uint32_t*)(smx + P1_KFL);
    uint32_t* vTh  = (uint32_t*)(smx + P1_VTH);
    uint32_t* vTl  = (uint32_t*)(smx + P1_VTL);
    float* ksum_sm = (float*)(smx + P1_KSUM);

    const int t = threadIdx.x, w = t >> 5, lane = t & 31;
    const int g = lane >> 2, tig = lane & 3;
    const int sx = blockIdx.x, b = blockIdx.y;
    const float* kp = k + ((size_t)b * SS + (size_t)sx * ROWS_P1) * DDIM;
    const float* vp = v + ((size_t)b * SS + (size_t)sx * ROWS_P1) * DDIM;
    const unsigned sstg = su32(smx);

    if (t < 64) ksum_sm[t] = 0.0f;

    // prefetch chunk 0 -> buf0, chunk 1 -> buf1
#pragma unroll
    for (int c = 0; c < 2; c++) {
        const float* kb = kp + (size_t)c * 2048;
        const float* vb = vp + (size_t)c * 2048;
        unsigned d0 = sstg + c * 16384;
        cp16(d0 + t * 16, kb + t * 4);
        cp16(d0 + (t + 256) * 16, kb + (t + 256) * 4);
        cp16(d0 + 8192 + t * 16, vb + t * 4);
        cp16(d0 + 8192 + (t + 256) * 16, vb + (t + 256) * 4);
        CP_COMMIT();
    }

    const int eb = (w & 3) * 16;        // warp m-tile (e rows)
    const int nb = (w >> 2) * 4;        // warp n-tile group (4 tiles of 8 d)
    float acc[4][4];
#pragma unroll
    for (int i = 0; i < 4; i++)
#pragma unroll
        for (int j = 0; j < 4; j++) acc[i][j] = 0.0f;
    float ksl = 0.0f;

    const int td = t & 63, sgb = (t >> 6) * 8;   // transpose-pass mapping
    const int wq = td * TP + (t >> 6) * 4;       // vectorized tile-store word base

    for (int ch = 0; ch < NCHUNK; ch++) {
        const int buf = ch & 1;
        if (ch < NCHUNK - 1) CP_WAIT(1); else CP_WAIT(0);
        __syncthreads();   // staging ready + previous mma done

        // transpose/convert: k -> fm -> split -> kfT ; v -> split -> vT (STS.128)
        {
            const float* sk = (const float*)(smx + buf * 16384);
            const float* sv = sk + 2048;
            float x[8];
            uint32_t h[4], l[4];
#pragma unroll
            for (int i = 0; i < 8; i++) {
                float y = fm(sk[(sgb + i) * 64 + td]);
                ksl += y; x[i] = y;
            }
#pragma unroll
            for (int j = 0; j < 4; j++) split2(x[2 * j], x[2 * j + 1], h[j], l[j]);
            *(uint4*)&kfTh[wq] = make_uint4(h[0], h[1], h[2], h[3]);
            *(uint4*)&kfTl[wq] = make_uint4(l[0], l[1], l[2], l[3]);
#pragma unroll
            for (int i = 0; i < 8; i++) x[i] = sv[(sgb + i) * 64 + td];
#pragma unroll
            for (int j = 0; j < 4; j++) split2(x[2 * j], x[2 * j + 1], h[j], l[j]);
            *(uint4*)&vTh[wq] = make_uint4(h[0], h[1], h[2], h[3]);
            *(uint4*)&vTl[wq] = make_uint4(l[0], l[1], l[2], l[3]);
        }
        __syncthreads();   // tiles ready, staging[buf] free

        if (ch + 2 < NCHUNK) {
            const float* kb = kp + (size_t)(ch + 2) * 2048;
            const float* vb = vp + (size_t)(ch + 2) * 2048;
            unsigned d0 = sstg + buf * 16384;
            cp16(d0 + t * 16, kb + t * 4);
            cp16(d0 + (t + 256) * 16, kb + (t + 256) * 4);
            cp16(d0 + 8192 + t * 16, vb + t * 4);
            cp16(d0 + 8192 + (t + 256) * 16, vb + (t + 256) * 4);
            CP_COMMIT();
        }

#pragma unroll
        for (int ks = 0; ks < 2; ks++) {
            const int sp = ks * 8 + tig;
            const int e0 = eb + g;
            uint32_t ah[4], al[4];
            ah[0] = vTh[e0 * TP + sp];       ah[1] = vTh[(e0 + 8) * TP + sp];
            ah[2] = vTh[e0 * TP + sp + 4];   ah[3] = vTh[(e0 + 8) * TP + sp + 4];
            al[0] = vTl[e0 * TP + sp];       al[1] = vTl[(e0 + 8) * TP + sp];
            al[2] = vTl[e0 * TP + sp + 4];   al[3] = vTl[(e0 + 8) * TP + sp + 4];
#pragma unroll
            for (int nt = 0; nt < 4; nt++) {
                const int d0 = (nb + nt) * 8 + g;
                uint32_t bh0 = kfTh[d0 * TP + sp], bh1 = kfTh[d0 * TP + sp + 4];
                uint32_t bl0 = kfTl[d0 * TP + sp], bl1 = kfTl[d0 * TP + sp + 4];
                mma_bf16(acc[nt], ah, bh0, bh1);
                mma_bf16(acc[nt], ah, bl0, bl1);
                mma_bf16(acc[nt], al, bh0, bh1);
            }
        }
    }

    // epilogue: partials [e][d] + ksum
    {
        float* op = g_part + ((size_t)sx * BB + b) * 4096;
#pragma unroll
        for (int nt = 0; nt < 4; nt++) {
            const int e0 = eb + g, d0 = (nb + nt) * 8 + tig * 2;
            *(float2*)(op + (size_t)e0 * 64 + d0)       = make_float2(acc[nt][0], acc[nt][1]);
            *(float2*)(op + (size_t)(e0 + 8) * 64 + d0) = make_float2(acc[nt][2], acc[nt][3]);
        }
    }
    atomicAdd(&ksum_sm[td], ksl);
    __syncthreads();
    if (t < 64) g_ksum_part[((size_t)sx * BB + b) * 64 + t] = ksum_sm[t];
}

// ---------------- combine: sum partials -> bf16 hi/lo word arrays ----------------
__global__ __launch_bounds__(256) void combine_kernel() {
    const int b = blockIdx.x, t = threadIdx.x;
    if (t < 64) {
        float s = 0.0f;
#pragma unroll
        for (int p = 0; p < SPLIT; p++) s += g_ksum_part[((size_t)p * BB + b) * 64 + t];
        g_ksum[(size_t)b * 64 + t] = s;
    }
#pragma unroll
    for (int i = 0; i < 8; i++) {
        const int p = t + i * 256;             // pair index = e*32 + word
        const int e = p >> 5, d0 = (p & 31) * 2;
        float s0 = 0.0f, s1 = 0.0f;
#pragma unroll
        for (int sp = 0; sp < SPLIT; sp++) {
            float2 x = *(const float2*)(g_part + ((size_t)sp * BB + b) * 4096 + (size_t)e * 64 + d0);
            s0 += x.x; s1 += x.y;
        }
        uint32_t hw, lw;
        split2(s0, s1, hw, lw);
        g_bhi[(size_t)b * 2048 + p] = hw;
        g_blo[(size_t)b * 2048 + p] = lw;
    }
}

// ---------------- phase 2: pipelined HMMA, 64-row chunks (measured best) -----
// D[s][e] = qf[s][d] * kv[d][e];  A = qf (m=s,k=d), B = kvT words (k=d,n=e)
#define NC2 16             // chunks per CTA (64 rows each -> 1024 rows)
#define QST 68             // q stage row stride (words)
#define AST 36             // tile row stride (words)
#define P2_ST0 0           // 64*QST*4 = 17408 B
#define P2_ST1 17408
#define P2_AH  34816       // [64][AST] words = 9216 B
#define P2_AL  44032
#define P2_BH  53248
#define P2_BL  62464
#define P2_KS  71680
#define P2_ID  71936
#define P2_SMEM 72192

__global__ __launch_bounds__(256) void phase2_kernel(const float* __restrict__ q,
                                                     float* __restrict__ o) {
    extern __shared__ char smx[];
    uint32_t* Ah = (uint32_t*)(smx + P2_AH);
    uint32_t* Al = (uint32_t*)(smx + P2_AL);
    uint32_t* Bh = (uint32_t*)(smx + P2_BH);
    uint32_t* Bl = (uint32_t*)(smx + P2_BL);
    float* ksum_s = (float*)(smx + P2_KS);
    float* iden   = (float*)(smx + P2_ID);
    const unsigned sbase = su32(smx);

    const int t = threadIdx.x, w = t >> 5, lane = t & 31;
    const int g = lane >> 2, tig = lane & 3;
    const int b = blockIdx.y;
    const size_t row0 = (size_t)b * SS + (size_t)blockIdx.x * (NC2 * 64);
    const float* qp = q + row0 * 64;
    float* op = o + row0 * 64;

    // prologue: B tiles + stage chunk0 (group 1), stage chunk1 (group 2)
    {
        const uint4* gh = (const uint4*)(g_bhi + (size_t)b * 2048);
        const uint4* gl = (const uint4*)(g_blo + (size_t)b * 2048);
#pragma unroll
        for (int i = 0; i < 2; i++) {
            int idx = t + i * 256;
            int e = idx >> 3, w4 = (idx & 7) * 4;
            cp16(sbase + P2_BH + (e * AST + w4) * 4, gh + idx);
            cp16(sbase + P2_BL + (e * AST + w4) * 4, gl + idx);
        }
#pragma unroll
        for (int i = 0; i < 4; i++) {
            int idx = t + i * 256;                 // 1024 cp16 per chunk
            int row = idx >> 4, c4 = (idx & 15) * 4;
            cp16(sbase + P2_ST0 + (row * QST + c4) * 4, qp + (size_t)row * 64 + c4);
        }
        CP_COMMIT();
#pragma unroll
        for (int i = 0; i < 4; i++) {
            int idx = t + i * 256;
            int row = idx >> 4, c4 = (idx & 15) * 4;
            cp16(sbase + P2_ST1 + (row * QST + c4) * 4, qp + (size_t)(64 + row) * 64 + c4);
        }
        CP_COMMIT();
    }
    if (t < 64) ksum_s[t] = g_ksum[(size_t)b * 64 + t];

    const int m0 = (w & 3) * 16;       // warp m-tile (rows)
    const int nbx = (w >> 2) * 32;     // warp n base (cols)

    for (int c = 0; c < NC2; c++) {
        const int buf = c & 1;
        if (c < NC2 - 1) CP_WAIT(1); else CP_WAIT(0);
        __syncthreads();   // stage[buf] ready + previous MMA done with A

        // convert: fm + denominator + hi/lo split into Ah/Al
        {
            const float* st = (const float*)(smx + (buf ? P2_ST1 : P2_ST0));
            const int row = t >> 2, c16 = (t & 3) * 16;
            const float* sr = st + row * QST + c16;
            float pden = 0.0f;
#pragma unroll
            for (int j = 0; j < 2; j++) {
                float4 x = *(const float4*)(sr + 8 * j);
                float4 y = *(const float4*)(sr + 8 * j + 4);
                x.x = fm(x.x); x.y = fm(x.y); x.z = fm(x.z); x.w = fm(x.w);
                y.x = fm(y.x); y.y = fm(y.y); y.z = fm(y.z); y.w = fm(y.w);
                const float* ks = &ksum_s[c16 + 8 * j];
                pden += x.x * ks[0] + x.y * ks[1] + x.z * ks[2] + x.w * ks[3]
                      + y.x * ks[4] + y.y * ks[5] + y.z * ks[6] + y.w * ks[7];
                uint32_t hw, lw;
                const int wb = row * AST + (t & 3) * 8 + j * 4;
                split2(x.x, x.y, hw, lw); Ah[wb + 0] = hw; Al[wb + 0] = lw;
                split2(x.z, x.w, hw, lw); Ah[wb + 1] = hw; Al[wb + 1] = lw;
                split2(y.x, y.y, hw, lw); Ah[wb + 2] = hw; Al[wb + 2] = lw;
                split2(y.z, y.w, hw, lw); Ah[wb + 3] = hw; Al[wb + 3] = lw;
            }
            pden += __shfl_xor_sync(0xffffffffu, pden, 1);
            pden += __shfl_xor_sync(0xffffffffu, pden, 2);
            if (!(t & 3)) iden[row] = 1.0f / fmaxf(pden, 1e-4f);
        }
        __syncthreads();   // A/iden ready, stage[buf] free

        if (c + 2 < NC2) {   // prefetch chunk c+2 (overlaps MMA below)
            const unsigned dst = sbase + (buf ? P2_ST1 : P2_ST0);
            const float* src = qp + (size_t)(c + 2) * 64 * 64;
#pragma unroll
            for (int i = 0; i < 4; i++) {
                int idx = t + i * 256;
                int row = idx >> 4, c4 = (idx & 15) * 4;
                cp16(dst + (row * QST + c4) * 4, src + (size_t)row * 64 + c4);
            }
            CP_COMMIT();
        }

        float acc[4][4];
#pragma unroll
        for (int i = 0; i < 4; i++)
#pragma unroll
            for (int j = 0; j < 4; j++) acc[i][j] = 0.0f;

#pragma unroll
        for (int ks = 0; ks < 4; ks++) {
            const int cc = ks * 8 + tig;
            const int r = m0 + g;
            uint32_t ah[4], al[4];
            ah[0] = Ah[r * AST + cc];       ah[1] = Ah[(r + 8) * AST + cc];
            ah[2] = Ah[r * AST + cc + 4];   ah[3] = Ah[(r + 8) * AST + cc + 4];
            al[0] = Al[r * AST + cc];       al[1] = Al[(r + 8) * AST + cc];
            al[2] = Al[r * AST + cc + 4];   al[3] = Al[(r + 8) * AST + cc + 4];
#pragma unroll
            for (int nt = 0; nt < 4; nt++) {
                const int e0 = nbx + nt * 8 + g;
                uint32_t bh0 = Bh[e0 * AST + cc], bh1 = Bh[e0 * AST + cc + 4];
                uint32_t bl0 = Bl[e0 * AST + cc], bl1 = Bl[e0 * AST + cc + 4];
                mma_bf16(acc[nt], ah, bh0, bh1);
                mma_bf16(acc[nt], ah, bl0, bl1);
                mma_bf16(acc[nt], al, bh0, bh1);
            }
        }

        // epilogue: scale by 1/deno and store
        {
            float* oc = op + (size_t)(c * 64) * 64;
            const int r = m0 + g;
            const float i0 = iden[r], i1 = iden[r + 8];
#pragma unroll
            for (int nt = 0; nt < 4; nt++) {
                const int e = nbx + nt * 8 + tig * 2;
                *(float2*)(oc + (size_t)r * 64 + e) =
                    make_float2(acc[nt][0] * i0, acc[nt][1] * i0);
                *(float2*)(oc + (size_t)(r + 8) * 64 + e) =
                    make_float2(acc[nt][2] * i1, acc[nt][3] * i1);
            }
        }
    }
}

// ---------------- launch ----------------
extern "C" void kernel_launch(void* const* d_in, const int* in_sizes, int n_in,
                              void* d_out, int out_size) {
    (void)in_sizes; (void)n_in; (void)out_size;
    const float* q = (const float*)d_in[0];
    const float* k = (const float*)d_in[1];
    const float* v = (const float*)d_in[2];
    float* o = (float*)d_out;

    cudaFuncSetAttribute(phase1_kernel, cudaFuncAttributeMaxDynamicSharedMemorySize, P1_SMEM);
    cudaFuncSetAttribute(phase2_kernel, cudaFuncAttributeMaxDynamicSharedMemorySize, P2_SMEM);

    dim3 g1(SPLIT, BB);
    phase1_kernel<<<g1, 256, P1_SMEM>>>(k, v);

    combine_kernel<<<BB, 256>>>();

    dim3 g2(SS / (NC2 * 64), BB);
    phase2_kernel<<<g2, 256, P2_SMEM>>>(q, o);
}

// round 14
// speedup vs baseline: 1.1941x; 1.0564x over previous
#include <cuda_runtime.h>
#include <cuda_bf16.h>
#include <cstdint>

#define BB 64
#define SS 8192
#define DDIM 64
#define SPLIT 16
#define ROWS_P1 (SS / SPLIT)   // 512
#define CH 32
#define NCHUNK (ROWS_P1 / CH)  // 16
#define TP 20                  // phase1 tile row stride (words): 4 mod 8 -> conflict-free

__device__ float    g_part[SPLIT * BB * DDIM * DDIM];
__device__ float    g_ksum_part[SPLIT * BB * DDIM];
__device__ uint32_t g_bhi[BB * DDIM * 32];   // kvT bf16-hi packed words [b][e][32]
__device__ uint32_t g_blo[BB * DDIM * 32];
__device__ float    g_ksum[BB * DDIM];

// ---------------- helpers ----------------
__device__ __forceinline__ float fm(float x) { return x > 0.0f ? x + 1.0f : __expf(x); }
__device__ __forceinline__ unsigned su32(const void* p) {
    unsigned r;
    asm("{ .reg .u64 t; cvta.to.shared.u64 t, %1; cvt.u32.u64 %0, t; }" : "=r"(r) : "l"(p));
    return r;
}
__device__ __forceinline__ void cp16(unsigned s, const void* g) {
    asm volatile("cp.async.cg.shared.global [%0], [%1], 16;" :: "r"(s), "l"(g));
}
#define CP_COMMIT() asm volatile("cp.async.commit_group;")
#define CP_WAIT(N)  asm volatile("cp.async.wait_group %0;" :: "n"(N))

__device__ __forceinline__ uint32_t pklh(float lo, float hi) {  // lo -> low 16
    uint32_t r;
    asm("cvt.rn.bf16x2.f32 %0, %1, %2;" : "=r"(r) : "f"(hi), "f"(lo));
    return r;
}
__device__ __forceinline__ uint32_t prmt7632(uint32_t a, uint32_t b) {
    uint32_t r; asm("prmt.b32 %0, %1, %2, 0x7632;" : "=r"(r) : "r"(a), "r"(b)); return r;
}
// truncation split of 2 fp32 -> packed bf16 hi word + bf16 lo word (x0 in low 16)
__device__ __forceinline__ void split2(float x0, float x1, uint32_t& hw, uint32_t& lw) {
    uint32_t u0 = __float_as_uint(x0), u1 = __float_as_uint(x1);
    hw = prmt7632(u0, u1);
    float l0 = x0 - __uint_as_float(u0 & 0xFFFF0000u);
    float l1 = x1 - __uint_as_float(u1 & 0xFFFF0000u);
    lw = pklh(l0, l1);
}
__device__ __forceinline__ void mma_bf16(float* c, const uint32_t* a, uint32_t b0, uint32_t b1) {
    asm volatile("mma.sync.aligned.m16n8k16.row.col.f32.bf16.bf16.f32 "
                 "{%0,%1,%2,%3},{%4,%5,%6,%7},{%8,%9},{%0,%1,%2,%3};"
                 : "+f"(c[0]), "+f"(c[1]), "+f"(c[2]), "+f"(c[3])
                 : "r"(a[0]), "r"(a[1]), "r"(a[2]), "r"(a[3]), "r"(b0), "r"(b1));
}
__device__ __forceinline__ void ldm_x4(uint32_t* r, unsigned a) {
    asm volatile("ldmatrix.sync.aligned.m8n8.x4.shared.b16 {%0,%1,%2,%3}, [%4];"
                 : "=r"(r[0]), "=r"(r[1]), "=r"(r[2]), "=r"(r[3]) : "r"(a));
}

// ---------------- phase 1: kvT partials via HMMA ------------------------------
// D[e][d] = sum_s v[s][e] * kf[s][d];  A = vT (m=e,k=s), B = kfT (k=s,n=d)
#define P1_STG   0        // 2 bufs x (k,v) x 2048 f32 = 32768 B
#define P1_KFH   32768    // [64][TP] words = 5120 B each
#define P1_KFL   37888
#define P1_VTH   43008
#define P1_VTL   48128
#define P1_KSUM  53248
#define P1_SMEM  53504

__global__ __launch_bounds__(256) void phase1_kernel(const float* __restrict__ k,
                                                     const float* __restrict__ v) {
    extern __shared__ char smx[];
    uint32_t* kfTh = (uint32_t*)(smx + P1_KFH);
    uint32_t* kfTl = (uint32_t*)(smx + P1_KFL);
    uint32_t* vTh  = (uint32_t*)(smx + P1_VTH);
    uint32_t* vTl  = (uint32_t*)(smx + P1_VTL);
    float* ksum_sm = (float*)(smx + P1_KSUM);

    const int t = threadIdx.x, w = t >> 5, lane = t & 31;
    const int g = lane >> 2, tig = lane & 3;
    const int sx = blockIdx.x, b = blockIdx.y;
    const float* kp = k + ((size_t)b * SS + (size_t)sx * ROWS_P1) * DDIM;
    const float* vp = v + ((size_t)b * SS + (size_t)sx * ROWS_P1) * DDIM;
    const unsigned sstg = su32(smx);

    if (t < 64) ksum_sm[t] = 0.0f;

    // prefetch chunk 0 -> buf0, chunk 1 -> buf1
#pragma unroll
    for (int c = 0; c < 2; c++) {
        const float* kb = kp + (size_t)c * 2048;
        const float* vb = vp + (size_t)c * 2048;
        unsigned d0 = sstg + c * 16384;
        cp16(d0 + t * 16, kb + t * 4);
        cp16(d0 + (t + 256) * 16, kb + (t + 256) * 4);
        cp16(d0 + 8192 + t * 16, vb + t * 4);
        cp16(d0 + 8192 + (t + 256) * 16, vb + (t + 256) * 4);
        CP_COMMIT();
    }

    const int eb = (w & 3) * 16;        // warp m-tile (e rows)
    const int nb = (w >> 2) * 4;        // warp n-tile group (4 tiles of 8 d)
    float acc[4][4];
#pragma unroll
    for (int i = 0; i < 4; i++)
#pragma unroll
        for (int j = 0; j < 4; j++) acc[i][j] = 0.0f;
    float ksl = 0.0f;

    const int td = t & 63, sgb = (t >> 6) * 8;   // transpose-pass mapping
    const int wq = td * TP + (t >> 6) * 4;       // vectorized tile-store word base

    // ldmatrix lane base byte-offsets (within each tile array)
    const int rowi = lane & 7;
    const unsigned aOff = ((eb + ((lane >> 3) & 1) * 8 + rowi) * TP + (lane >> 4) * 4) * 4;
    const unsigned bOff = ((nb * 8 + (lane >> 4) * 8 + rowi) * TP + ((lane >> 3) & 1) * 4) * 4;
    const unsigned bVTh = su32(vTh), bVTl = su32(vTl);
    const unsigned bKFh = su32(kfTh), bKFl = su32(kfTl);

    for (int ch = 0; ch < NCHUNK; ch++) {
        const int buf = ch & 1;
        if (ch < NCHUNK - 1) CP_WAIT(1); else CP_WAIT(0);
        __syncthreads();   // staging ready + previous mma done

        // transpose/convert: k -> fm -> split -> kfT ; v -> split -> vT (STS.128)
        {
            const float* sk = (const float*)(smx + buf * 16384);
            const float* sv = sk + 2048;
            float x[8];
            uint32_t h[4], l[4];
#pragma unroll
            for (int i = 0; i < 8; i++) {
                float y = fm(sk[(sgb + i) * 64 + td]);
                ksl += y; x[i] = y;
            }
#pragma unroll
            for (int j = 0; j < 4; j++) split2(x[2 * j], x[2 * j + 1], h[j], l[j]);
            *(uint4*)&kfTh[wq] = make_uint4(h[0], h[1], h[2], h[3]);
            *(uint4*)&kfTl[wq] = make_uint4(l[0], l[1], l[2], l[3]);
#pragma unroll
            for (int i = 0; i < 8; i++) x[i] = sv[(sgb + i) * 64 + td];
#pragma unroll
            for (int j = 0; j < 4; j++) split2(x[2 * j], x[2 * j + 1], h[j], l[j]);
            *(uint4*)&vTh[wq] = make_uint4(h[0], h[1], h[2], h[3]);
            *(uint4*)&vTl[wq] = make_uint4(l[0], l[1], l[2], l[3]);
        }
        __syncthreads();   // tiles ready, staging[buf] free

        if (ch + 2 < NCHUNK) {
            const float* kb = kp + (size_t)(ch + 2) * 2048;
            const float* vb = vp + (size_t)(ch + 2) * 2048;
            unsigned d0 = sstg + buf * 16384;
            cp16(d0 + t * 16, kb + t * 4);
            cp16(d0 + (t + 256) * 16, kb + (t + 256) * 4);
            cp16(d0 + 8192 + t * 16, vb + t * 4);
            cp16(d0 + 8192 + (t + 256) * 16, vb + (t + 256) * 4);
            CP_COMMIT();
        }

#pragma unroll
        for (int ks = 0; ks < 2; ks++) {
            const unsigned kso = ks * 32;        // +8 words per k-step
            uint32_t ah[4], al[4], bh[8], bl[8];
            ldm_x4(ah, bVTh + aOff + kso);
            ldm_x4(al, bVTl + aOff + kso);
            ldm_x4(bh, bKFh + bOff + kso);
            ldm_x4(bh + 4, bKFh + bOff + 16 * TP * 4 + kso);
            ldm_x4(bl, bKFl + bOff + kso);
            ldm_x4(bl + 4, bKFl + bOff + 16 * TP * 4 + kso);
#pragma unroll
            for (int nt = 0; nt < 4; nt++) {
                mma_bf16(acc[nt], ah, bh[2 * nt], bh[2 * nt + 1]);
                mma_bf16(acc[nt], ah, bl[2 * nt], bl[2 * nt + 1]);
                mma_bf16(acc[nt], al, bh[2 * nt], bh[2 * nt + 1]);
            }
        }
    }

    // epilogue: partials [e][d] + ksum
    {
        float* op = g_part + ((size_t)sx * BB + b) * 4096;
#pragma unroll
        for (int nt = 0; nt < 4; nt++) {
            const int e0 = eb + g, d0 = (nb + nt) * 8 + tig * 2;
            *(float2*)(op + (size_t)e0 * 64 + d0)       = make_float2(acc[nt][0], acc[nt][1]);
            *(float2*)(op + (size_t)(e0 + 8) * 64 + d0) = make_float2(acc[nt][2], acc[nt][3]);
        }
    }
    atomicAdd(&ksum_sm[td], ksl);
    __syncthreads();
    if (t < 64) g_ksum_part[((size_t)sx * BB + b) * 64 + t] = ksum_sm[t];
}

// ---------------- combine: sum partials -> bf16 hi/lo word arrays ----------------
__global__ __launch_bounds__(256) void combine_kernel() {
    const int b = blockIdx.x, t = threadIdx.x;
    if (t < 64) {
        float s = 0.0f;
#pragma unroll
        for (int p = 0; p < SPLIT; p++) s += g_ksum_part[((size_t)p * BB + b) * 64 + t];
        g_ksum[(size_t)b * 64 + t] = s;
    }
#pragma unroll
    for (int i = 0; i < 8; i++) {
        const int p = t + i * 256;             // pair index = e*32 + word
        const int e = p >> 5, d0 = (p & 31) * 2;
        float s0 = 0.0f, s1 = 0.0f;
#pragma unroll
        for (int sp = 0; sp < SPLIT; sp++) {
            float2 x = *(const float2*)(g_part + ((size_t)sp * BB + b) * 4096 + (size_t)e * 64 + d0);
            s0 += x.x; s1 += x.y;
        }
        uint32_t hw, lw;
        split2(s0, s1, hw, lw);
        g_bhi[(size_t)b * 2048 + p] = hw;
        g_blo[(size_t)b * 2048 + p] = lw;
    }
}

// ---------------- phase 2: pipelined HMMA, 64-row chunks ----------------------
// D[s][e] = qf[s][d] * kv[d][e];  A = qf (m=s,k=d), B = kvT words (k=d,n=e)
#define NC2 16             // chunks per CTA (64 rows each -> 1024 rows)
#define QST 68             // q stage row stride (words)
#define AST 36             // tile row stride (words)
#define P2_ST0 0           // 64*QST*4 = 17408 B
#define P2_ST1 17408
#define P2_AH  34816       // [64][AST] words = 9216 B
#define P2_AL  44032
#define P2_BH  53248
#define P2_BL  62464
#define P2_KS  71680
#define P2_ID  71936
#define P2_SMEM 72192

__global__ __launch_bounds__(256) void phase2_kernel(const float* __restrict__ q,
                                                     float* __restrict__ o) {
    extern __shared__ char smx[];
    uint32_t* Ah = (uint32_t*)(smx + P2_AH);
    uint32_t* Al = (uint32_t*)(smx + P2_AL);
    uint32_t* Bh = (uint32_t*)(smx + P2_BH);
    uint32_t* Bl = (uint32_t*)(smx + P2_BL);
    float* ksum_s = (float*)(smx + P2_KS);
    float* iden   = (float*)(smx + P2_ID);
    const unsigned sbase = su32(smx);

    const int t = threadIdx.x, w = t >> 5, lane = t & 31;
    const int g = lane >> 2, tig = lane & 3;
    const int b = blockIdx.y;
    const size_t row0 = (size_t)b * SS + (size_t)blockIdx.x * (NC2 * 64);
    const float* qp = q + row0 * 64;
    float* op = o + row0 * 64;

    // prologue: B tiles + stage chunk0 (group 1), stage chunk1 (group 2)
    {
        const uint4* gh = (const uint4*)(g_bhi + (size_t)b * 2048);
        const uint4* gl = (const uint4*)(g_blo + (size_t)b * 2048);
#pragma unroll
        for (int i = 0; i < 2; i++) {
            int idx = t + i * 256;
            int e = idx >> 3, w4 = (idx & 7) * 4;
            cp16(sbase + P2_BH + (e * AST + w4) * 4, gh + idx);
            cp16(sbase + P2_BL + (e * AST + w4) * 4, gl + idx);
        }
#pragma unroll
        for (int i = 0; i < 4; i++) {
            int idx = t + i * 256;                 // 1024 cp16 per chunk
            int row = idx >> 4, c4 = (idx & 15) * 4;
            cp16(sbase + P2_ST0 + (row * QST + c4) * 4, qp + (size_t)row * 64 + c4);
        }
        CP_COMMIT();
#pragma unroll
        for (int i = 0; i < 4; i++) {
            int idx = t + i * 256;
            int row = idx >> 4, c4 = (idx & 15) * 4;
            cp16(sbase + P2_ST1 + (row * QST + c4) * 4, qp + (size_t)(64 + row) * 64 + c4);
        }
        CP_COMMIT();
    }
    if (t < 64) ksum_s[t] = g_ksum[(size_t)b * 64 + t];

    const int m0 = (w & 3) * 16;       // warp m-tile (rows)
    const int nbx = (w >> 2) * 32;     // warp n base (cols)

    // ldmatrix lane base byte-offsets
    const int rowi = lane & 7;
    const unsigned aOff = ((m0 + ((lane >> 3) & 1) * 8 + rowi) * AST + (lane >> 4) * 4) * 4;
    const unsigned bOff = ((nbx + (lane >> 4) * 8 + rowi) * AST + ((lane >> 3) & 1) * 4) * 4;
    const unsigned bAh = su32(Ah), bAl = su32(Al);
    const unsigned bBh = su32(Bh), bBl = su32(Bl);

    for (int c = 0; c < NC2; c++) {
        const int buf = c & 1;
        if (c < NC2 - 1) CP_WAIT(1); else CP_WAIT(0);
        __syncthreads();   // stage[buf] ready + previous MMA done with A

        // convert: fm + denominator + hi/lo split into Ah/Al (STS.128)
        {
            const float* st = (const float*)(smx + (buf ? P2_ST1 : P2_ST0));
            const int row = t >> 2, c16 = (t & 3) * 16;
            const float* sr = st + row * QST + c16;
            float pden = 0.0f;
#pragma unroll
            for (int j = 0; j < 2; j++) {
                float4 x = *(const float4*)(sr + 8 * j);
                float4 y = *(const float4*)(sr + 8 * j + 4);
                x.x = fm(x.x); x.y = fm(x.y); x.z = fm(x.z); x.w = fm(x.w);
                y.x = fm(y.x); y.y = fm(y.y); y.z = fm(y.z); y.w = fm(y.w);
                const float* ks = &ksum_s[c16 + 8 * j];
                pden += x.x * ks[0] + x.y * ks[1] + x.z * ks[2] + x.w * ks[3]
                      + y.x * ks[4] + y.y * ks[5] + y.z * ks[6] + y.w * ks[7];
                uint32_t h0, l0, h1, l1, h2, l2, h3, l3;
                split2(x.x, x.y, h0, l0);
                split2(x.z, x.w, h1, l1);
                split2(y.x, y.y, h2, l2);
                split2(y.z, y.w, h3, l3);
                const int wb = row * AST + (t & 3) * 8 + j * 4;
                *(uint4*)&Ah[wb] = make_uint4(h0, h1, h2, h3);
                *(uint4*)&Al[wb] = make_uint4(l0, l1, l2, l3);
            }
            pden += __shfl_xor_sync(0xffffffffu, pden, 1);
            pden += __shfl_xor_sync(0xffffffffu, pden, 2);
            if (!(t & 3)) iden[row] = 1.0f / fmaxf(pden, 1e-4f);
        }
        __syncthreads();   // A/iden ready, stage[buf] free

        if (c + 2 < NC2) {   // prefetch chunk c+2 (overlaps MMA below)
            const unsigned dst = sbase + (buf ? P2_ST1 : P2_ST0);
            const float* src = qp + (size_t)(c + 2) * 64 * 64;
#pragma unroll
            for (int i = 0; i < 4; i++) {
                int idx = t + i * 256;
                int row = idx >> 4, c4 = (idx & 15) * 4;
                cp16(dst + (row * QST + c4) * 4, src + (size_t)row * 64 + c4);
            }
            CP_COMMIT();
        }

        float acc[4][4];
#pragma unroll
        for (int i = 0; i < 4; i++)
#pragma unroll
            for (int j = 0; j < 4; j++) acc[i][j] = 0.0f;

#pragma unroll
        for (int ks = 0; ks < 4; ks++) {
            const unsigned kso = ks * 32;
            uint32_t ah[4], al[4], bh[8], bl[8];
            ldm_x4(ah, bAh + aOff + kso);
            ldm_x4(al, bAl + aOff + kso);
            ldm_x4(bh, bBh + bOff + kso);
            ldm_x4(bh + 4, bBh + bOff + 16 * AST * 4 + kso);
            ldm_x4(bl, bBl + bOff + kso);
            ldm_x4(bl + 4, bBl + bOff + 16 * AST * 4 + kso);
#pragma unroll
            for (int nt = 0; nt < 4; nt++) {
                mma_bf16(acc[nt], ah, bh[2 * nt], bh[2 * nt + 1]);
                mma_bf16(acc[nt], ah, bl[2 * nt], bl[2 * nt + 1]);
                mma_bf16(acc[nt], al, bh[2 * nt], bh[2 * nt + 1]);
            }
        }

        // epilogue: scale by 1/deno and store
        {
            float* oc = op + (size_t)(c * 64) * 64;
            const int r = m0 + g;
            const float i0 = iden[r], i1 = iden[r + 8];
#pragma unroll
            for (int nt = 0; nt < 4; nt++) {
                const int e = nbx + nt * 8 + tig * 2;
                *(float2*)(oc + (size_t)r * 64 + e) =
                    make_float2(acc[nt][0] * i0, acc[nt][1] * i0);
                *(float2*)(oc + (size_t)(r + 8) * 64 + e) =
                    make_float2(acc[nt][2] * i1, acc[nt][3] * i1);
            }
        }
    }
}

// ---------------- launch ----------------
extern "C" void kernel_launch(void* const* d_in, const int* in_sizes, int n_in,
                              void* d_out, int out_size) {
    (void)in_sizes; (void)n_in; (void)out_size;
    const float* q = (const float*)d_in[0];
    const float* k = (const float*)d_in[1];
    const float* v = (const float*)d_in[2];
    float* o = (float*)d_out;

    cudaFuncSetAttribute(phase1_kernel, cudaFuncAttributeMaxDynamicSharedMemorySize, P1_SMEM);
    cudaFuncSetAttribute(phase2_kernel, cudaFuncAttributeMaxDynamicSharedMemorySize, P2_SMEM);

    dim3 g1(SPLIT, BB);
    phase1_kernel<<<g1, 256, P1_SMEM>>>(k, v);

    combine_kernel<<<BB, 256>>>();

    dim3 g2(SS / (NC2 * 64), BB);
    phase2_kernel<<<g2, 256, P2_SMEM>>>(q, o);
}